// round 1
// baseline (speedup 1.0000x reference)
#include <cuda_runtime.h>
#include <cuda_bf16.h>

#define BATCH 2048
#define LR 49          // K_REG
#define DIM 2048

// __device__ scratch (allocation-free)
__device__ __nv_bfloat16 wv_bf[LR * DIM];     // bf16 copy of W_v
__device__ float g_scr[BATCH * LR];           // W_gt = h_t @ W_g^T
__device__ float sent_scr[BATCH];             // sentinel logit

// ---------------------------------------------------------------------------
// Kernel 1: g[b,k], sent[b]; also W_v -> bf16 conversion
// grid 256, block 256, 8 batches per CTA
// ---------------------------------------------------------------------------
__global__ __launch_bounds__(256) void k1(
    const float* __restrict__ h_t, const float* __restrict__ s_t,
    const float* __restrict__ W_v, const float* __restrict__ W_g,
    const float* __restrict__ W_s, const float* __restrict__ w_h_s)
{
    __shared__ float4 xch[2 * 8 * 32];   // [mat][batch][32 float4] = 8KB
    __shared__ float pb[98][2][8];
    __shared__ float valall[98][8];

    const int tid = threadIdx.x;

    // W_v -> bf16 (first 98 CTAs, 1024 floats each)
    if (blockIdx.x < 98) {
        float4 v = ((const float4*)W_v)[blockIdx.x * 256 + tid];
        __nv_bfloat162 lo = __floats2bfloat162_rn(v.x, v.y);
        __nv_bfloat162 hi = __floats2bfloat162_rn(v.z, v.w);
        __nv_bfloat162* dst = (__nv_bfloat162*)(wv_bf) + (size_t)(blockIdx.x * 256 + tid) * 2;
        dst[0] = lo; dst[1] = hi;
    }

    const int b0 = blockIdx.x * 8;
    const int pp = tid >> 1;       // 0..127
    const int half = tid & 1;
    const bool act = pp < 98;
    const int mat = (pp >= LR) ? 1 : 0;
    const int kk = mat ? pp - LR : pp;
    const float* Wrow = (mat ? W_s : W_g) + (size_t)kk * DIM;

    float acc[8];
    #pragma unroll
    for (int i = 0; i < 8; i++) acc[i] = 0.f;

    for (int ch = 0; ch < 16; ch++) {          // D chunks of 128 floats
        #pragma unroll
        for (int it = 0; it < 2; it++) {
            int idx = tid + it * 256;
            int m = idx >> 8, rem = idx & 255;
            int bi = rem >> 5, q = rem & 31;
            const float* srcp = (m ? s_t : h_t) + (size_t)(b0 + bi) * DIM + ch * 128 + q * 4;
            xch[idx] = *(const float4*)srcp;
        }
        __syncthreads();
        if (act) {
            const float4* wp = (const float4*)(Wrow + ch * 128 + half * 64);
            #pragma unroll 4
            for (int j = 0; j < 16; j++) {
                float4 w = wp[j];
                #pragma unroll
                for (int bi = 0; bi < 8; bi++) {
                    float4 x = xch[mat * 256 + bi * 32 + half * 16 + j];
                    acc[bi] += w.x * x.x + w.y * x.y + w.z * x.z + w.w * x.w;
                }
            }
        }
        __syncthreads();
    }
    if (act) {
        #pragma unroll
        for (int bi = 0; bi < 8; bi++) pb[pp][half][bi] = acc[bi];
    }
    __syncthreads();
    if (tid < 98) {
        #pragma unroll
        for (int bi = 0; bi < 8; bi++) {
            float v = pb[tid][0][bi] + pb[tid][1][bi];
            valall[tid][bi] = v;
            if (tid < LR) g_scr[(size_t)(b0 + bi) * LR + tid] = v;
        }
    }
    __syncthreads();
    {
        const int w = tid >> 5, lane = tid & 31;   // warp w handles batch b0+w
        float s = 0.f;
        if (lane < LR) s = tanhf(valall[LR + lane][w] + valall[lane][w]) * w_h_s[lane];
        if (lane + 32 < LR)
            s += tanhf(valall[LR + lane + 32][w] + valall[lane + 32][w]) * w_h_s[lane + 32];
        #pragma unroll
        for (int o = 16; o > 0; o >>= 1) s += __shfl_xor_sync(0xffffffffu, s, o);
        if (lane == 0) sent_scr[b0 + w] = s;
    }
}

// ---------------------------------------------------------------------------
// Kernel 2: fused W_vV GEMM (bf16 mma.sync) + tanh/softmax + c_t + output
// grid 1024 (2 batches per CTA), block 256 (8 warps = 8 m-strips of M=128)
// ---------------------------------------------------------------------------
__global__ __launch_bounds__(256) void k2(
    const float* __restrict__ V, const float* __restrict__ h_t,
    const float* __restrict__ s_t, const float* __restrict__ w_h,
    float* __restrict__ out)
{
    // SMEM: union of {A(18432) + B(9216)} with Wv result (33280), then extras
    __shared__ __align__(16) unsigned char smraw[35088];

    const int tid = threadIdx.x;
    const int warp = tid >> 5, lane = tid & 31;
    const int b0 = blockIdx.x * 2, b1 = b0 + 1;

    __nv_bfloat16* A_sm = (__nv_bfloat16*)smraw;             // 128 rows x 72 bf16
    __nv_bfloat16* B_sm = (__nv_bfloat16*)(smraw + 18432);   // 64 rows x 72 bf16
    unsigned* Au = (unsigned*)A_sm;
    unsigned* Bu = (unsigned*)B_sm;
    float (*Wv)[65] = (float (*)[65])smraw;                  // aliases A/B after GEMM
    float* gk      = (float*)(smraw + 33280);   // [128]: 0..48 b0, 64..112 b1
    float* wh      = (float*)(smraw + 33792);   // [64]
    float* zsm     = (float*)(smraw + 34048);   // [128]
    float* alpha_s = (float*)(smraw + 34560);   // [128]
    float* bet     = (float*)(smraw + 35072);   // [2]

    // zero the whole tile region once (pad rows/cols stay 0 forever)
    for (int i = tid; i < (18432 + 9216) / 4; i += 256) ((unsigned*)smraw)[i] = 0u;
    __syncthreads();

    float acc[8][4];
    #pragma unroll
    for (int j = 0; j < 8; j++) {
        #pragma unroll
        for (int c = 0; c < 4; c++) acc[j][c] = 0.f;
    }

    const float* Vb0 = V + (size_t)b0 * LR * DIM;
    const float* Vb1 = V + (size_t)b1 * LR * DIM;

    for (int ch = 0; ch < 32; ch++) {            // D chunks of 64
        // A tile: b0 -> rows 0..48, b1 -> rows 64..112 (fp32 -> bf16)
        for (int idx = tid; idx < 784; idx += 256) {
            int row = idx >> 4, c4 = idx & 15;
            float4 v = *(const float4*)(Vb0 + (size_t)row * DIM + ch * 64 + c4 * 4);
            __nv_bfloat162 p0 = __floats2bfloat162_rn(v.x, v.y);
            __nv_bfloat162 p1 = __floats2bfloat162_rn(v.z, v.w);
            __nv_bfloat162* d = (__nv_bfloat162*)(A_sm + row * 72 + c4 * 4);
            d[0] = p0; d[1] = p1;
        }
        for (int idx = tid; idx < 784; idx += 256) {
            int row = idx >> 4, c4 = idx & 15;
            float4 v = *(const float4*)(Vb1 + (size_t)row * DIM + ch * 64 + c4 * 4);
            __nv_bfloat162 p0 = __floats2bfloat162_rn(v.x, v.y);
            __nv_bfloat162 p1 = __floats2bfloat162_rn(v.z, v.w);
            __nv_bfloat162* d = (__nv_bfloat162*)(A_sm + (64 + row) * 72 + c4 * 4);
            d[0] = p0; d[1] = p1;
        }
        // B tile: W_v rows (bf16 scratch), 49 x 64
        for (int idx = tid; idx < 392; idx += 256) {
            int row = idx >> 3, q = idx & 7;
            const uint4* src = (const uint4*)(wv_bf + (size_t)row * DIM + ch * 64 + q * 8);
            *(uint4*)(B_sm + row * 72 + q * 8) = *src;
        }
        __syncthreads();

        #pragma unroll
        for (int st = 0; st < 4; st++) {         // k16 steps within chunk
            int baseu = st * 8;
            int arow = warp * 16 + (lane >> 2);
            int ai = arow * 36 + baseu + (lane & 3);
            unsigned a0 = Au[ai];
            unsigned a1 = Au[ai + 8 * 36];
            unsigned a2 = Au[ai + 4];
            unsigned a3 = Au[ai + 8 * 36 + 4];
            #pragma unroll
            for (int j = 0; j < 8; j++) {
                int bidx = (j * 8 + (lane >> 2)) * 36 + baseu + (lane & 3);
                unsigned bb0 = Bu[bidx];
                unsigned bb1 = Bu[bidx + 4];
                asm volatile(
                    "mma.sync.aligned.m16n8k16.row.col.f32.bf16.bf16.f32 "
                    "{%0,%1,%2,%3}, {%4,%5,%6,%7}, {%8,%9}, {%0,%1,%2,%3};\n"
                    : "+f"(acc[j][0]), "+f"(acc[j][1]), "+f"(acc[j][2]), "+f"(acc[j][3])
                    : "r"(a0), "r"(a1), "r"(a2), "r"(a3), "r"(bb0), "r"(bb1));
            }
        }
        __syncthreads();
    }

    // ---- epilogue: dump accumulators into aliased SMEM ----
    #pragma unroll
    for (int j = 0; j < 8; j++) {
        int r = warp * 16 + (lane >> 2);
        int c = j * 8 + 2 * (lane & 3);
        Wv[r][c]         = acc[j][0];
        Wv[r][c + 1]     = acc[j][1];
        Wv[r + 8][c]     = acc[j][2];
        Wv[r + 8][c + 1] = acc[j][3];
    }
    if (tid < LR) {
        gk[tid]      = g_scr[(size_t)b0 * LR + tid];
        gk[64 + tid] = g_scr[(size_t)b1 * LR + tid];
        wh[tid]      = w_h[tid];
    }
    __syncthreads();

    // z_t[l] = sum_k tanh(WvV[l,k] + g[k]) * w_h[k]
    {
        int lv = tid >> 1, q = tid & 1;    // lv 0..127
        int gb = lv & 64;
        float z = 0.f;
        for (int k = q; k < LR; k += 2)
            z += tanhf(Wv[lv][k] + gk[gb + k]) * wh[k];
        z += __shfl_xor_sync(0xffffffffu, z, 1);
        if (q == 0) zsm[lv] = z;
    }
    __syncthreads();

    // softmax over 50 logits, warps 0/1 (one per batch)
    if (warp < 2) {
        float v0 = (lane < LR) ? zsm[warp * 64 + lane] : -1e30f;
        float v1 = -1e30f;
        if (lane + 32 < LR)       v1 = zsm[warp * 64 + lane + 32];
        else if (lane + 32 == LR) v1 = sent_scr[b0 + warp];
        float m = fmaxf(v0, v1);
        #pragma unroll
        for (int o = 16; o > 0; o >>= 1) m = fmaxf(m, __shfl_xor_sync(0xffffffffu, m, o));
        float e0 = __expf(v0 - m), e1 = __expf(v1 - m);
        float s = e0 + e1;
        #pragma unroll
        for (int o = 16; o > 0; o >>= 1) s += __shfl_xor_sync(0xffffffffu, s, o);
        float inv = 1.f / s;
        if (lane < LR)       alpha_s[warp * 64 + lane]      = e0 * inv;
        if (lane + 32 < LR)  alpha_s[warp * 64 + lane + 32] = e1 * inv;
        if (lane == 17)      bet[warp] = e1 * inv;   // logit index 49
    }
    __syncthreads();

    // pass 2: c_t + output (V re-read, ideally L2-warm)
    float be0 = bet[0], be1 = bet[1];
    #pragma unroll
    for (int r = 0; r < 4; r++) {
        int pbatch = r >> 1;
        int d4 = tid + (r & 1) * 256;
        const float* Vb = pbatch ? Vb1 : Vb0;
        const float* ap = alpha_s + pbatch * 64;
        float cx = 0.f, cy = 0.f, cz = 0.f, cw = 0.f;
        #pragma unroll 7
        for (int l = 0; l < LR; l++) {
            float4 v = *(const float4*)(Vb + (size_t)l * DIM + d4 * 4);
            float a = ap[l];
            cx += a * v.x; cy += a * v.y; cz += a * v.z; cw += a * v.w;
        }
        int b = pbatch ? b1 : b0;
        float be = pbatch ? be1 : be0;
        float om = 1.f - be;
        float4 s4 = *(const float4*)(s_t + (size_t)b * DIM + d4 * 4);
        float4 h4 = *(const float4*)(h_t + (size_t)b * DIM + d4 * 4);
        float4 o;
        o.x = be * s4.x + om * cx + h4.x;
        o.y = be * s4.y + om * cy + h4.y;
        o.z = be * s4.z + om * cz + h4.z;
        o.w = be * s4.w + om * cw + h4.w;
        *(float4*)(out + (size_t)b * DIM + d4 * 4) = o;
    }
}

extern "C" void kernel_launch(void* const* d_in, const int* in_sizes, int n_in,
                              void* d_out, int out_size) {
    const float* V     = (const float*)d_in[0];
    const float* h_t   = (const float*)d_in[1];
    const float* s_t   = (const float*)d_in[2];
    const float* W_v   = (const float*)d_in[3];
    const float* W_g   = (const float*)d_in[4];
    const float* W_s   = (const float*)d_in[5];
    const float* w_h   = (const float*)d_in[6];
    const float* w_h_s = (const float*)d_in[7];
    float* out = (float*)d_out;

    k1<<<256, 256>>>(h_t, s_t, W_v, W_g, W_s, w_h_s);
    k2<<<1024, 256>>>(V, h_t, s_t, w_h, out);
}

// round 2
// speedup vs baseline: 1.4999x; 1.4999x over previous
#include <cuda_runtime.h>
#include <cuda_bf16.h>

#define BATCH 2048
#define LR 49          // K_REG
#define DIM 2048

// __device__ scratch (allocation-free)
__device__ __nv_bfloat16 wv_bf[LR * DIM];     // bf16 copy of W_v
__device__ float g_scr[BATCH * LR];           // W_gt = h_t @ W_g^T
__device__ float sent_scr[BATCH];             // sentinel logit

// ---------------------------------------------------------------------------
// Kernel 1: g[b,k], sent[b]; also W_v -> bf16 conversion
// grid 256, block 256, 8 batches per CTA. W staged through SMEM (coalesced).
// SMEM layout trick: row stride 72 floats, within-row: half*36 + c
//   -> LDS banks (8*pp + 4*half + 4*j) mod 32 : conflict-free fragment reads
// ---------------------------------------------------------------------------
__global__ __launch_bounds__(256) void k1(
    const float* __restrict__ h_t, const float* __restrict__ s_t,
    const float* __restrict__ W_v, const float* __restrict__ W_g,
    const float* __restrict__ W_s, const float* __restrict__ w_h_s)
{
    __shared__ __align__(16) float Wsm[98 * 72];   // 28224 B
    __shared__ __align__(16) float xsm[16 * 72];   // 4608 B
    __shared__ float pb[98][2][8];
    __shared__ float valall[98][8];

    const int tid = threadIdx.x;

    // W_v -> bf16 (first 98 CTAs, 1024 floats each)
    if (blockIdx.x < 98) {
        float4 v = ((const float4*)W_v)[blockIdx.x * 256 + tid];
        __nv_bfloat162 lo = __floats2bfloat162_rn(v.x, v.y);
        __nv_bfloat162 hi = __floats2bfloat162_rn(v.z, v.w);
        __nv_bfloat162* dst = (__nv_bfloat162*)(wv_bf) + (size_t)(blockIdx.x * 256 + tid) * 2;
        dst[0] = lo; dst[1] = hi;
    }

    const int b0 = blockIdx.x * 8;
    const int pp = tid >> 1;       // 0..127  (row of concat [W_g; W_s])
    const int half = tid & 1;      // owns 32 of the 64-float chunk
    const bool act = pp < 98;
    const int mat = (pp >= LR) ? 1 : 0;

    float acc[8];
    #pragma unroll
    for (int i = 0; i < 8; i++) acc[i] = 0.f;

    const float* wbase = Wsm + pp * 72 + half * 36;
    const float* xbase = xsm + mat * 8 * 72 + half * 36;

    #pragma unroll 1
    for (int ch = 0; ch < 32; ch++) {          // D chunks of 64 floats
        // stage W chunk: 98 rows x 16 float4, warp-contiguous loads
        for (int idx = tid; idx < 1568; idx += 256) {
            int row = idx >> 4, q = idx & 15;
            const float* src = (row < LR ? W_g + (size_t)row * DIM
                                         : W_s + (size_t)(row - LR) * DIM)
                               + ch * 64 + q * 4;
            float4 v = *(const float4*)src;
            *(float4*)(Wsm + row * 72 + q * 4 + ((q >= 8) ? 4 : 0)) = v;
        }
        // stage x chunk: 2 mats x 8 batches x 16 float4 = 256 float4
        {
            int m = tid >> 7, rem = tid & 127;
            int bi = rem >> 4, q = rem & 15;
            const float* src = (m ? s_t : h_t) + (size_t)(b0 + bi) * DIM + ch * 64 + q * 4;
            float4 v = *(const float4*)src;
            *(float4*)(xsm + (m * 8 + bi) * 72 + q * 4 + ((q >= 8) ? 4 : 0)) = v;
        }
        __syncthreads();
        if (act) {
            #pragma unroll
            for (int j = 0; j < 8; j++) {
                float4 w = *(const float4*)(wbase + j * 4);
                #pragma unroll
                for (int bi = 0; bi < 8; bi++) {
                    float4 x = *(const float4*)(xbase + bi * 72 + j * 4);
                    acc[bi] += w.x * x.x + w.y * x.y + w.z * x.z + w.w * x.w;
                }
            }
        }
        __syncthreads();
    }

    if (act) {
        #pragma unroll
        for (int bi = 0; bi < 8; bi++) pb[pp][half][bi] = acc[bi];
    }
    __syncthreads();
    if (tid < 98) {
        #pragma unroll
        for (int bi = 0; bi < 8; bi++) {
            float v = pb[tid][0][bi] + pb[tid][1][bi];
            valall[tid][bi] = v;
            if (tid < LR) g_scr[(size_t)(b0 + bi) * LR + tid] = v;
        }
    }
    __syncthreads();
    {
        const int w = tid >> 5, lane = tid & 31;   // warp w handles batch b0+w
        float s = 0.f;
        if (lane < LR) s = tanhf(valall[LR + lane][w] + valall[lane][w]) * w_h_s[lane];
        if (lane + 32 < LR)
            s += tanhf(valall[LR + lane + 32][w] + valall[lane + 32][w]) * w_h_s[lane + 32];
        #pragma unroll
        for (int o = 16; o > 0; o >>= 1) s += __shfl_xor_sync(0xffffffffu, s, o);
        if (lane == 0) sent_scr[b0 + w] = s;
    }
}

// ---------------------------------------------------------------------------
// Kernel 2: fused W_vV GEMM (bf16 mma.sync, register-prefetch pipelined)
//           + tanh/softmax + c_t + output
// grid 1024 (2 batches per CTA), block 256 (8 warps = 8 m-strips of M=128)
// ---------------------------------------------------------------------------
__global__ __launch_bounds__(256) void k2(
    const float* __restrict__ V, const float* __restrict__ h_t,
    const float* __restrict__ s_t, const float* __restrict__ w_h,
    float* __restrict__ out)
{
    // SMEM: union of {A(18432) + B(9216)} with Wv result (33280), then extras
    __shared__ __align__(16) unsigned char smraw[35088];

    const int tid = threadIdx.x;
    const int warp = tid >> 5, lane = tid & 31;
    const int b0 = blockIdx.x * 2, b1 = b0 + 1;

    __nv_bfloat16* A_sm = (__nv_bfloat16*)smraw;             // 128 rows x 72 bf16
    __nv_bfloat16* B_sm = (__nv_bfloat16*)(smraw + 18432);   // 64 rows x 72 bf16
    unsigned* Au = (unsigned*)A_sm;
    unsigned* Bu = (unsigned*)B_sm;
    float (*Wv)[65] = (float (*)[65])smraw;                  // aliases A/B after GEMM
    float* gk      = (float*)(smraw + 33280);   // [128]: 0..48 b0, 64..112 b1
    float* wh      = (float*)(smraw + 33792);   // [64]
    float* zsm     = (float*)(smraw + 34048);   // [128]
    float* alpha_s = (float*)(smraw + 34560);   // [128]
    float* bet     = (float*)(smraw + 35072);   // [2]

    // zero the whole tile region once (pad rows/cols stay 0 forever)
    for (int i = tid; i < (18432 + 9216) / 4; i += 256) ((unsigned*)smraw)[i] = 0u;

    const float* Vb0 = V + (size_t)b0 * LR * DIM;
    const float* Vb1 = V + (size_t)b1 * LR * DIM;

    // per-thread prefetch slot descriptors
    // A: 2*49*16 = 1568 float4 slots;  B: 49*8 = 392 uint4 slots
    const float* asrc[7]; int adst[7]; bool aact[7];
    #pragma unroll
    for (int s = 0; s < 7; s++) {
        int a = s * 256 + tid;
        aact[s] = (a < 1568);
        int batch = (a >= 784) ? 1 : 0;
        int idx = a - 784 * batch;
        int row = idx >> 4, c4 = idx & 15;
        if (!aact[s]) { row = 0; c4 = 0; }
        asrc[s] = (batch ? Vb1 : Vb0) + (size_t)row * DIM + c4 * 4;
        adst[s] = (batch * 64 + row) * 72 + c4 * 4;
    }
    const __nv_bfloat16* bsrc[2]; int bdst[2]; bool bact[2];
    #pragma unroll
    for (int s = 0; s < 2; s++) {
        int bidx = s * 256 + tid;
        bact[s] = (bidx < 392);
        int row = bidx >> 3, q = bidx & 7;
        if (!bact[s]) { row = 0; q = 0; }
        bsrc[s] = wv_bf + (size_t)row * DIM + q * 8;
        bdst[s] = row * 72 + q * 8;
    }

    float acc[8][4];
    #pragma unroll
    for (int j = 0; j < 8; j++) {
        #pragma unroll
        for (int c = 0; c < 4; c++) acc[j][c] = 0.f;
    }

    float4 ra[7]; uint4 rb[2];
    // prefetch chunk 0
    #pragma unroll
    for (int s = 0; s < 7; s++) if (aact[s]) ra[s] = *(const float4*)(asrc[s]);
    #pragma unroll
    for (int s = 0; s < 2; s++) if (bact[s]) rb[s] = *(const uint4*)(bsrc[s]);

    __syncthreads();   // zero-fill complete before first stores land next to it

    #pragma unroll 1
    for (int ch = 0; ch < 32; ch++) {            // D chunks of 64
        // store current chunk regs -> smem (fp32 -> bf16)
        #pragma unroll
        for (int s = 0; s < 7; s++) {
            if (aact[s]) {
                __nv_bfloat162 p0 = __floats2bfloat162_rn(ra[s].x, ra[s].y);
                __nv_bfloat162 p1 = __floats2bfloat162_rn(ra[s].z, ra[s].w);
                __nv_bfloat162* d = (__nv_bfloat162*)(A_sm + adst[s]);
                d[0] = p0; d[1] = p1;
            }
        }
        #pragma unroll
        for (int s = 0; s < 2; s++)
            if (bact[s]) *(uint4*)(B_sm + bdst[s]) = rb[s];
        __syncthreads();

        // issue next chunk's global loads (consumed only after the MMAs below)
        if (ch + 1 < 32) {
            #pragma unroll
            for (int s = 0; s < 7; s++)
                if (aact[s]) ra[s] = *(const float4*)(asrc[s] + (ch + 1) * 64);
            #pragma unroll
            for (int s = 0; s < 2; s++)
                if (bact[s]) rb[s] = *(const uint4*)(bsrc[s] + (ch + 1) * 64);
        }

        #pragma unroll
        for (int st = 0; st < 4; st++) {         // k16 steps within chunk
            int baseu = st * 8;
            int arow = warp * 16 + (lane >> 2);
            int ai = arow * 36 + baseu + (lane & 3);
            unsigned a0 = Au[ai];
            unsigned a1 = Au[ai + 8 * 36];
            unsigned a2 = Au[ai + 4];
            unsigned a3 = Au[ai + 8 * 36 + 4];
            #pragma unroll
            for (int j = 0; j < 8; j++) {
                int bidx = (j * 8 + (lane >> 2)) * 36 + baseu + (lane & 3);
                unsigned bb0 = Bu[bidx];
                unsigned bb1 = Bu[bidx + 4];
                asm volatile(
                    "mma.sync.aligned.m16n8k16.row.col.f32.bf16.bf16.f32 "
                    "{%0,%1,%2,%3}, {%4,%5,%6,%7}, {%8,%9}, {%0,%1,%2,%3};\n"
                    : "+f"(acc[j][0]), "+f"(acc[j][1]), "+f"(acc[j][2]), "+f"(acc[j][3])
                    : "r"(a0), "r"(a1), "r"(a2), "r"(a3), "r"(bb0), "r"(bb1));
            }
        }
        __syncthreads();
    }

    // ---- epilogue: dump accumulators into aliased SMEM ----
    #pragma unroll
    for (int j = 0; j < 8; j++) {
        int r = warp * 16 + (lane >> 2);
        int c = j * 8 + 2 * (lane & 3);
        Wv[r][c]         = acc[j][0];
        Wv[r][c + 1]     = acc[j][1];
        Wv[r + 8][c]     = acc[j][2];
        Wv[r + 8][c + 1] = acc[j][3];
    }
    if (tid < LR) {
        gk[tid]      = g_scr[(size_t)b0 * LR + tid];
        gk[64 + tid] = g_scr[(size_t)b1 * LR + tid];
        wh[tid]      = w_h[tid];
    }
    __syncthreads();

    // z_t[l] = sum_k tanh(WvV[l,k] + g[k]) * w_h[k]
    {
        int lv = tid >> 1, q = tid & 1;    // lv 0..127
        int gb = lv & 64;
        float z = 0.f;
        for (int k = q; k < LR; k += 2)
            z += tanhf(Wv[lv][k] + gk[gb + k]) * wh[k];
        z += __shfl_xor_sync(0xffffffffu, z, 1);
        if (q == 0) zsm[lv] = z;
    }
    __syncthreads();

    // softmax over 50 logits, warps 0/1 (one per batch)
    if (warp < 2) {
        float v0 = (lane < LR) ? zsm[warp * 64 + lane] : -1e30f;
        float v1 = -1e30f;
        if (lane + 32 < LR)       v1 = zsm[warp * 64 + lane + 32];
        else if (lane + 32 == LR) v1 = sent_scr[b0 + warp];
        float m = fmaxf(v0, v1);
        #pragma unroll
        for (int o = 16; o > 0; o >>= 1) m = fmaxf(m, __shfl_xor_sync(0xffffffffu, m, o));
        float e0 = __expf(v0 - m), e1 = __expf(v1 - m);
        float s = e0 + e1;
        #pragma unroll
        for (int o = 16; o > 0; o >>= 1) s += __shfl_xor_sync(0xffffffffu, s, o);
        float inv = 1.f / s;
        if (lane < LR)       alpha_s[warp * 64 + lane]      = e0 * inv;
        if (lane + 32 < LR)  alpha_s[warp * 64 + lane + 32] = e1 * inv;
        if (lane == 17)      bet[warp] = e1 * inv;   // logit index 49
    }
    __syncthreads();

    // pass 2: c_t + output. Both d-halves of a batch fused -> 14 loads/unroll
    #pragma unroll 1
    for (int pbv = 0; pbv < 2; pbv++) {
        const float* Vb = pbv ? Vb1 : Vb0;
        const float* ap = alpha_s + pbv * 64;
        float c0x = 0.f, c0y = 0.f, c0z = 0.f, c0w = 0.f;
        float c1x = 0.f, c1y = 0.f, c1z = 0.f, c1w = 0.f;
        #pragma unroll 7
        for (int l = 0; l < LR; l++) {
            float a = ap[l];
            float4 v0 = *(const float4*)(Vb + (size_t)l * DIM + tid * 4);
            float4 v1 = *(const float4*)(Vb + (size_t)l * DIM + 1024 + tid * 4);
            c0x += a * v0.x; c0y += a * v0.y; c0z += a * v0.z; c0w += a * v0.w;
            c1x += a * v1.x; c1y += a * v1.y; c1z += a * v1.z; c1w += a * v1.w;
        }
        int b = pbv ? b1 : b0;
        float be = bet[pbv];
        float om = 1.f - be;
        {
            float4 s4 = *(const float4*)(s_t + (size_t)b * DIM + tid * 4);
            float4 h4 = *(const float4*)(h_t + (size_t)b * DIM + tid * 4);
            float4 o;
            o.x = be * s4.x + om * c0x + h4.x;
            o.y = be * s4.y + om * c0y + h4.y;
            o.z = be * s4.z + om * c0z + h4.z;
            o.w = be * s4.w + om * c0w + h4.w;
            *(float4*)(out + (size_t)b * DIM + tid * 4) = o;
        }
        {
            float4 s4 = *(const float4*)(s_t + (size_t)b * DIM + 1024 + tid * 4);
            float4 h4 = *(const float4*)(h_t + (size_t)b * DIM + 1024 + tid * 4);
            float4 o;
            o.x = be * s4.x + om * c1x + h4.x;
            o.y = be * s4.y + om * c1y + h4.y;
            o.z = be * s4.z + om * c1z + h4.z;
            o.w = be * s4.w + om * c1w + h4.w;
            *(float4*)(out + (size_t)b * DIM + 1024 + tid * 4) = o;
        }
    }
}

extern "C" void kernel_launch(void* const* d_in, const int* in_sizes, int n_in,
                              void* d_out, int out_size) {
    const float* V     = (const float*)d_in[0];
    const float* h_t   = (const float*)d_in[1];
    const float* s_t   = (const float*)d_in[2];
    const float* W_v   = (const float*)d_in[3];
    const float* W_g   = (const float*)d_in[4];
    const float* W_s   = (const float*)d_in[5];
    const float* w_h   = (const float*)d_in[6];
    const float* w_h_s = (const float*)d_in[7];
    float* out = (float*)d_out;

    k1<<<256, 256>>>(h_t, s_t, W_v, W_g, W_s, w_h_s);
    k2<<<1024, 256>>>(V, h_t, s_t, w_h, out);
}

// round 3
// speedup vs baseline: 1.7745x; 1.1831x over previous
#include <cuda_runtime.h>
#include <cuda_bf16.h>

#define BATCH 2048
#define LR 49          // K_REG
#define DIM 2048

// __device__ scratch (allocation-free)
__device__ __nv_bfloat16 wv_bf[LR * DIM];     // bf16 copy of W_v
__device__ float g_scr[BATCH * LR];           // h_t @ W_g^T
__device__ float S_scr[BATCH * LR];           // s_t @ W_s^T
__device__ float sent_scr[BATCH];             // sentinel logit

// ---------------------------------------------------------------------------
// Kernel 1: MMA GEMM. grid 32: bid<16 -> g = h_t@W_g^T tile, else S = s_t@W_s^T
// M=128 batches, N=56 (49 used), K=2048 in 32 chunks of 64. block 256.
// Also converts W_v -> bf16 (spread over all 32 CTAs).
// ---------------------------------------------------------------------------
__global__ __launch_bounds__(256) void k1(
    const float* __restrict__ h_t, const float* __restrict__ s_t,
    const float* __restrict__ W_v, const float* __restrict__ W_g,
    const float* __restrict__ W_s)
{
    __shared__ __align__(16) unsigned char raw[29184];
    __nv_bfloat16* A_sm = (__nv_bfloat16*)raw;            // 128 x 72 bf16
    __nv_bfloat16* B_sm = (__nv_bfloat16*)(raw + 18432);  // 56 x 72 bf16
    unsigned* Au = (unsigned*)A_sm;
    unsigned* Bu = (unsigned*)B_sm;
    float (*P)[57] = (float (*)[57])raw;                  // 128 x 57 fp32 (alias)

    const int tid = threadIdx.x;
    const int warp = tid >> 5, lane = tid & 31;
    const int typ = blockIdx.x >> 4;          // 0: g (h_t,W_g)   1: S (s_t,W_s)
    const int b0 = (blockIdx.x & 15) * 128;
    const float* X = typ ? s_t : h_t;
    const float* W = typ ? W_s : W_g;
    float* dst = typ ? S_scr : g_scr;

    // W_v -> bf16, 784 float4 per CTA
    {
        int base = blockIdx.x * 784;
        for (int i = tid; i < 784; i += 256) {
            float4 v = ((const float4*)W_v)[base + i];
            __nv_bfloat162 lo = __floats2bfloat162_rn(v.x, v.y);
            __nv_bfloat162 hi = __floats2bfloat162_rn(v.z, v.w);
            __nv_bfloat162* d = (__nv_bfloat162*)(wv_bf) + (size_t)(base + i) * 2;
            d[0] = lo; d[1] = hi;
        }
    }

    // zero smem (pad cols / pad rows stay zero)
    for (int i = tid; i < 29184 / 4; i += 256) ((unsigned*)raw)[i] = 0u;

    // prefetch slot descriptors
    const float* asrc[8]; int adst[8];
    #pragma unroll
    for (int s = 0; s < 8; s++) {
        int a = s * 256 + tid;               // 0..2047
        int row = a >> 4, c4 = a & 15;
        asrc[s] = X + (size_t)(b0 + row) * DIM + c4 * 4;
        adst[s] = row * 72 + c4 * 4;
    }
    const float* bsrc[4]; int bdst[4]; bool bact[4]; bool bzero[4];
    #pragma unroll
    for (int s = 0; s < 4; s++) {
        int idx = s * 256 + tid;             // 0..1023, active < 896
        bact[s] = (idx < 896);
        int row = idx >> 4, c4 = idx & 15;
        bzero[s] = (row >= LR);
        int rowc = (row < LR) ? row : 0;
        bsrc[s] = W + (size_t)rowc * DIM + c4 * 4;
        bdst[s] = row * 72 + c4 * 4;
    }

    float acc[7][4];
    #pragma unroll
    for (int j = 0; j < 7; j++) { acc[j][0]=acc[j][1]=acc[j][2]=acc[j][3]=0.f; }

    float4 ra[8], rbv[4];
    #pragma unroll
    for (int s = 0; s < 8; s++) ra[s] = *(const float4*)(asrc[s]);
    #pragma unroll
    for (int s = 0; s < 4; s++) if (bact[s]) rbv[s] = *(const float4*)(bsrc[s]);
    __syncthreads();   // zero-fill done

    #pragma unroll 1
    for (int ch = 0; ch < 32; ch++) {
        #pragma unroll
        for (int s = 0; s < 8; s++) {
            __nv_bfloat162 p0 = __floats2bfloat162_rn(ra[s].x, ra[s].y);
            __nv_bfloat162 p1 = __floats2bfloat162_rn(ra[s].z, ra[s].w);
            __nv_bfloat162* d = (__nv_bfloat162*)(A_sm + adst[s]);
            d[0] = p0; d[1] = p1;
        }
        #pragma unroll
        for (int s = 0; s < 4; s++) {
            if (bact[s]) {
                float4 v = bzero[s] ? make_float4(0.f,0.f,0.f,0.f) : rbv[s];
                __nv_bfloat162 p0 = __floats2bfloat162_rn(v.x, v.y);
                __nv_bfloat162 p1 = __floats2bfloat162_rn(v.z, v.w);
                __nv_bfloat162* d = (__nv_bfloat162*)(B_sm + bdst[s]);
                d[0] = p0; d[1] = p1;
            }
        }
        __syncthreads();
        if (ch + 1 < 32) {
            #pragma unroll
            for (int s = 0; s < 8; s++) ra[s] = *(const float4*)(asrc[s] + (ch + 1) * 64);
            #pragma unroll
            for (int s = 0; s < 4; s++) if (bact[s]) rbv[s] = *(const float4*)(bsrc[s] + (ch + 1) * 64);
        }
        #pragma unroll
        for (int st = 0; st < 4; st++) {
            int baseu = st * 8;
            int ai = (warp * 16 + (lane >> 2)) * 36 + baseu + (lane & 3);
            unsigned a0 = Au[ai];
            unsigned a1 = Au[ai + 8 * 36];
            unsigned a2 = Au[ai + 4];
            unsigned a3 = Au[ai + 8 * 36 + 4];
            #pragma unroll
            for (int j = 0; j < 7; j++) {
                int bidx = (j * 8 + (lane >> 2)) * 36 + baseu + (lane & 3);
                unsigned bb0 = Bu[bidx];
                unsigned bb1 = Bu[bidx + 4];
                asm volatile(
                    "mma.sync.aligned.m16n8k16.row.col.f32.bf16.bf16.f32 "
                    "{%0,%1,%2,%3}, {%4,%5,%6,%7}, {%8,%9}, {%0,%1,%2,%3};\n"
                    : "+f"(acc[j][0]), "+f"(acc[j][1]), "+f"(acc[j][2]), "+f"(acc[j][3])
                    : "r"(a0), "r"(a1), "r"(a2), "r"(a3), "r"(bb0), "r"(bb1));
            }
        }
        __syncthreads();
    }

    // epilogue: acc -> P (alias) -> gmem
    #pragma unroll
    for (int j = 0; j < 7; j++) {
        int r = warp * 16 + (lane >> 2);
        int c = j * 8 + 2 * (lane & 3);
        P[r][c]         = acc[j][0];
        P[r][c + 1]     = acc[j][1];
        P[r + 8][c]     = acc[j][2];
        P[r + 8][c + 1] = acc[j][3];
    }
    __syncthreads();
    for (int idx = tid; idx < 128 * LR; idx += 256) {
        int row = idx / LR, k = idx - row * LR;
        dst[(size_t)(b0 + row) * LR + k] = P[row][k];
    }
}

// ---------------------------------------------------------------------------
// Kernel 1b: sent[b] = sum_k tanh(S[b,k] + g[b,k]) * w_h_s[k]
// grid 256, block 256: warp per batch
// ---------------------------------------------------------------------------
__global__ __launch_bounds__(256) void k1b(const float* __restrict__ w_h_s)
{
    const int warp = threadIdx.x >> 5, lane = threadIdx.x & 31;
    const int b = blockIdx.x * 8 + warp;
    float s = 0.f;
    if (lane < LR)
        s = tanhf(g_scr[(size_t)b * LR + lane] + S_scr[(size_t)b * LR + lane]) * w_h_s[lane];
    if (lane + 32 < LR)
        s += tanhf(g_scr[(size_t)b * LR + lane + 32] + S_scr[(size_t)b * LR + lane + 32]) * w_h_s[lane + 32];
    #pragma unroll
    for (int o = 16; o > 0; o >>= 1) s += __shfl_xor_sync(0xffffffffu, s, o);
    if (lane == 0) sent_scr[b] = s;
}

// ---------------------------------------------------------------------------
// Kernel 2: fused W_vV GEMM (bf16 mma.sync, 2-deep register pipeline)
//           + tanh/softmax + c_t + output.  Forced 1 CTA/SM via dynamic smem
//           so pass-2 V re-reads hit L2 (148 x 802KB = 119MB <= L2).
// grid 1024 (2 batches per CTA), block 256 (8 warps)
// ---------------------------------------------------------------------------
__global__ __launch_bounds__(256) void k2(
    const float* __restrict__ V, const float* __restrict__ h_t,
    const float* __restrict__ s_t, const float* __restrict__ w_h,
    float* __restrict__ out)
{
    extern __shared__ __align__(16) unsigned char smraw[];

    const int tid = threadIdx.x;
    const int warp = tid >> 5, lane = tid & 31;
    const int b0 = blockIdx.x * 2, b1 = b0 + 1;

    __nv_bfloat16* A_sm = (__nv_bfloat16*)smraw;             // 128 x 72 bf16
    __nv_bfloat16* B_sm = (__nv_bfloat16*)(smraw + 18432);   // 64 x 72 bf16
    unsigned* Au = (unsigned*)A_sm;
    unsigned* Bu = (unsigned*)B_sm;
    float (*Wv)[65] = (float (*)[65])smraw;                  // aliases A/B after GEMM
    float* gk      = (float*)(smraw + 33280);   // [128]
    float* wh      = (float*)(smraw + 33792);   // [64]
    float* zsm     = (float*)(smraw + 34048);   // [128]
    float* alpha_s = (float*)(smraw + 34560);   // [128]
    float* bet     = (float*)(smraw + 35072);   // [2]

    for (int i = tid; i < (18432 + 9216) / 4; i += 256) ((unsigned*)smraw)[i] = 0u;

    const float* Vb0 = V + (size_t)b0 * LR * DIM;
    const float* Vb1 = V + (size_t)b1 * LR * DIM;

    // per-thread prefetch slot descriptors
    const float* asrc[7]; int adst[7]; bool aact[7];
    #pragma unroll
    for (int s = 0; s < 7; s++) {
        int a = s * 256 + tid;
        aact[s] = (a < 1568);
        int batch = (a >= 784) ? 1 : 0;
        int idx = a - 784 * batch;
        int row = idx >> 4, c4 = idx & 15;
        if (!aact[s]) { row = 0; c4 = 0; }
        asrc[s] = (batch ? Vb1 : Vb0) + (size_t)row * DIM + c4 * 4;
        adst[s] = (batch * 64 + row) * 72 + c4 * 4;
    }
    const __nv_bfloat16* bsrc[2]; int bdst[2]; bool bact[2];
    #pragma unroll
    for (int s = 0; s < 2; s++) {
        int bidx = s * 256 + tid;
        bact[s] = (bidx < 392);
        int row = bidx >> 3, q = bidx & 7;
        if (!bact[s]) { row = 0; q = 0; }
        bsrc[s] = wv_bf + (size_t)row * DIM + q * 8;
        bdst[s] = row * 72 + q * 8;
    }

    float acc[8][4];
    #pragma unroll
    for (int j = 0; j < 8; j++) { acc[j][0]=acc[j][1]=acc[j][2]=acc[j][3]=0.f; }

    float4 ra0[7], ra1[7]; uint4 rb0[2], rb1[2];
    #pragma unroll
    for (int s = 0; s < 7; s++) if (aact[s]) ra0[s] = *(const float4*)(asrc[s]);
    #pragma unroll
    for (int s = 0; s < 2; s++) if (bact[s]) rb0[s] = *(const uint4*)(bsrc[s]);
    #pragma unroll
    for (int s = 0; s < 7; s++) if (aact[s]) ra1[s] = *(const float4*)(asrc[s] + 64);
    #pragma unroll
    for (int s = 0; s < 2; s++) if (bact[s]) rb1[s] = *(const uint4*)(bsrc[s] + 64);

    __syncthreads();   // zero-fill complete

    auto step = [&](int ch, float4 (&raS)[7], uint4 (&rbS)[2]) {
        #pragma unroll
        for (int s = 0; s < 7; s++) {
            if (aact[s]) {
                __nv_bfloat162 p0 = __floats2bfloat162_rn(raS[s].x, raS[s].y);
                __nv_bfloat162 p1 = __floats2bfloat162_rn(raS[s].z, raS[s].w);
                __nv_bfloat162* d = (__nv_bfloat162*)(A_sm + adst[s]);
                d[0] = p0; d[1] = p1;
            }
        }
        #pragma unroll
        for (int s = 0; s < 2; s++)
            if (bact[s]) *(uint4*)(B_sm + bdst[s]) = rbS[s];
        __syncthreads();

        if (ch + 2 < 32) {
            #pragma unroll
            for (int s = 0; s < 7; s++)
                if (aact[s]) raS[s] = *(const float4*)(asrc[s] + (ch + 2) * 64);
            #pragma unroll
            for (int s = 0; s < 2; s++)
                if (bact[s]) rbS[s] = *(const uint4*)(bsrc[s] + (ch + 2) * 64);
        }

        #pragma unroll
        for (int st = 0; st < 4; st++) {
            int baseu = st * 8;
            int ai = (warp * 16 + (lane >> 2)) * 36 + baseu + (lane & 3);
            unsigned a0 = Au[ai];
            unsigned a1 = Au[ai + 8 * 36];
            unsigned a2 = Au[ai + 4];
            unsigned a3 = Au[ai + 8 * 36 + 4];
            #pragma unroll
            for (int j = 0; j < 8; j++) {
                int bidx = (j * 8 + (lane >> 2)) * 36 + baseu + (lane & 3);
                unsigned bb0 = Bu[bidx];
                unsigned bb1 = Bu[bidx + 4];
                asm volatile(
                    "mma.sync.aligned.m16n8k16.row.col.f32.bf16.bf16.f32 "
                    "{%0,%1,%2,%3}, {%4,%5,%6,%7}, {%8,%9}, {%0,%1,%2,%3};\n"
                    : "+f"(acc[j][0]), "+f"(acc[j][1]), "+f"(acc[j][2]), "+f"(acc[j][3])
                    : "r"(a0), "r"(a1), "r"(a2), "r"(a3), "r"(bb0), "r"(bb1));
            }
        }
        __syncthreads();
    };

    #pragma unroll 1
    for (int ch = 0; ch < 32; ch += 2) {
        step(ch, ra0, rb0);
        step(ch + 1, ra1, rb1);
    }

    // ---- epilogue ----
    #pragma unroll
    for (int j = 0; j < 8; j++) {
        int r = warp * 16 + (lane >> 2);
        int c = j * 8 + 2 * (lane & 3);
        Wv[r][c]         = acc[j][0];
        Wv[r][c + 1]     = acc[j][1];
        Wv[r + 8][c]     = acc[j][2];
        Wv[r + 8][c + 1] = acc[j][3];
    }
    if (tid < LR) {
        gk[tid]      = g_scr[(size_t)b0 * LR + tid];
        gk[64 + tid] = g_scr[(size_t)b1 * LR + tid];
        wh[tid]      = w_h[tid];
    }
    __syncthreads();

    {
        int lv = tid >> 1, q = tid & 1;
        int gb = lv & 64;
        float z = 0.f;
        for (int k = q; k < LR; k += 2)
            z += tanhf(Wv[lv][k] + gk[gb + k]) * wh[k];
        z += __shfl_xor_sync(0xffffffffu, z, 1);
        if (q == 0) zsm[lv] = z;
    }
    __syncthreads();

    if (warp < 2) {
        float v0 = (lane < LR) ? zsm[warp * 64 + lane] : -1e30f;
        float v1 = -1e30f;
        if (lane + 32 < LR)       v1 = zsm[warp * 64 + lane + 32];
        else if (lane + 32 == LR) v1 = sent_scr[b0 + warp];
        float m = fmaxf(v0, v1);
        #pragma unroll
        for (int o = 16; o > 0; o >>= 1) m = fmaxf(m, __shfl_xor_sync(0xffffffffu, m, o));
        float e0 = __expf(v0 - m), e1 = __expf(v1 - m);
        float s = e0 + e1;
        #pragma unroll
        for (int o = 16; o > 0; o >>= 1) s += __shfl_xor_sync(0xffffffffu, s, o);
        float inv = 1.f / s;
        if (lane < LR)       alpha_s[warp * 64 + lane]      = e0 * inv;
        if (lane + 32 < LR)  alpha_s[warp * 64 + lane + 32] = e1 * inv;
        if (lane == 17)      bet[warp] = e1 * inv;
    }
    __syncthreads();

    // pass 2: c_t + output (V re-read, L2-warm at 1 CTA/SM)
    #pragma unroll 1
    for (int pbv = 0; pbv < 2; pbv++) {
        const float* Vb = pbv ? Vb1 : Vb0;
        const float* ap = alpha_s + pbv * 64;
        float c0x = 0.f, c0y = 0.f, c0z = 0.f, c0w = 0.f;
        float c1x = 0.f, c1y = 0.f, c1z = 0.f, c1w = 0.f;
        #pragma unroll 7
        for (int l = 0; l < LR; l++) {
            float a = ap[l];
            float4 v0 = *(const float4*)(Vb + (size_t)l * DIM + tid * 4);
            float4 v1 = *(const float4*)(Vb + (size_t)l * DIM + 1024 + tid * 4);
            c0x += a * v0.x; c0y += a * v0.y; c0z += a * v0.z; c0w += a * v0.w;
            c1x += a * v1.x; c1y += a * v1.y; c1z += a * v1.z; c1w += a * v1.w;
        }
        int b = pbv ? b1 : b0;
        float be = bet[pbv];
        float om = 1.f - be;
        {
            float4 s4 = *(const float4*)(s_t + (size_t)b * DIM + tid * 4);
            float4 h4 = *(const float4*)(h_t + (size_t)b * DIM + tid * 4);
            float4 o;
            o.x = be * s4.x + om * c0x + h4.x;
            o.y = be * s4.y + om * c0y + h4.y;
            o.z = be * s4.z + om * c0z + h4.z;
            o.w = be * s4.w + om * c0w + h4.w;
            *(float4*)(out + (size_t)b * DIM + tid * 4) = o;
        }
        {
            float4 s4 = *(const float4*)(s_t + (size_t)b * DIM + 1024 + tid * 4);
            float4 h4 = *(const float4*)(h_t + (size_t)b * DIM + 1024 + tid * 4);
            float4 o;
            o.x = be * s4.x + om * c1x + h4.x;
            o.y = be * s4.y + om * c1y + h4.y;
            o.z = be * s4.z + om * c1z + h4.z;
            o.w = be * s4.w + om * c1w + h4.w;
            *(float4*)(out + (size_t)b * DIM + 1024 + tid * 4) = o;
        }
    }
}

extern "C" void kernel_launch(void* const* d_in, const int* in_sizes, int n_in,
                              void* d_out, int out_size) {
    const float* V     = (const float*)d_in[0];
    const float* h_t   = (const float*)d_in[1];
    const float* s_t   = (const float*)d_in[2];
    const float* W_v   = (const float*)d_in[3];
    const float* W_g   = (const float*)d_in[4];
    const float* W_s   = (const float*)d_in[5];
    const float* w_h   = (const float*)d_in[6];
    const float* w_h_s = (const float*)d_in[7];
    float* out = (float*)d_out;

    static bool attr_set = false;
    if (!attr_set) {
        cudaFuncSetAttribute(k2, cudaFuncAttributeMaxDynamicSharedMemorySize, 131072);
        attr_set = true;
    }

    k1<<<32, 256>>>(h_t, s_t, W_v, W_g, W_s);
    k1b<<<256, 256>>>(w_h_s);
    // 128KB dynamic smem forces 1 CTA/SM -> pass-2 V re-reads stay L2-resident
    k2<<<1024, 256, 131072>>>(V, h_t, s_t, w_h, out);
}